// round 1
// baseline (speedup 1.0000x reference)
#include <cuda_runtime.h>
#include <cstdint>

#define T_STEPS 2048
#define BATCH   32
#define INDIM   512
#define HID     512
#define G4      2048   // 4*HID

// -------- persistent device scratch (static __device__ arrays are the sanctioned
// workaround for the no-allocation rule) --------
__device__ float    g_xp[(size_t)T_STEPS * BATCH * G4];   // 512 MB: x_proj[t][b][g]
__device__ float    g_h[2][BATCH * HID];                  // double-buffered hidden state
__device__ unsigned g_bar;                                // grid barrier counter

// ============================================================================
// Kernel A: x_proj[m][n] = sum_k seq[m][k] * W_ih[n][k] + b_ih[n] + b_hh[n]
//   m = t*32+b in [0,65536), n in [0,2048), k in [0,512)
//   64x64 block tile, BK=32, 4x4 per-thread tile, 256 threads.
// ============================================================================
__global__ __launch_bounds__(256) void xproj_kernel(
    const float* __restrict__ seq,
    const float* __restrict__ Wih,
    const float* __restrict__ bih,
    const float* __restrict__ bhh)
{
    __shared__ float As[64 * 33];
    __shared__ float Bs[64 * 33];

    const int tid = threadIdx.x;
    const int m0  = blockIdx.y * 64;
    const int n0  = blockIdx.x * 64;
    const int ty  = tid >> 4;          // 0..15
    const int tx  = tid & 15;          // 0..15
    const int rr0 = ty * 4;
    const int cc0 = tx * 4;

    float acc[4][4] = {};

    for (int kb = 0; kb < 512; kb += 32) {
        // cooperative tile loads (float4, coalesced)
        #pragma unroll
        for (int l = 0; l < 2; ++l) {
            int idx = tid + l * 256;
            int row = idx >> 3;
            int q   = (idx & 7) << 2;
            float4 va = *(const float4*)(seq + (size_t)(m0 + row) * 512 + kb + q);
            As[row * 33 + q + 0] = va.x;
            As[row * 33 + q + 1] = va.y;
            As[row * 33 + q + 2] = va.z;
            As[row * 33 + q + 3] = va.w;
            float4 vb = *(const float4*)(Wih + (size_t)(n0 + row) * 512 + kb + q);
            Bs[row * 33 + q + 0] = vb.x;
            Bs[row * 33 + q + 1] = vb.y;
            Bs[row * 33 + q + 2] = vb.z;
            Bs[row * 33 + q + 3] = vb.w;
        }
        __syncthreads();

        #pragma unroll 8
        for (int kk = 0; kk < 32; ++kk) {
            float a[4], b[4];
            #pragma unroll
            for (int i = 0; i < 4; ++i) a[i] = As[(rr0 + i) * 33 + kk];
            #pragma unroll
            for (int j = 0; j < 4; ++j) b[j] = Bs[(cc0 + j) * 33 + kk];
            #pragma unroll
            for (int i = 0; i < 4; ++i)
                #pragma unroll
                for (int j = 0; j < 4; ++j)
                    acc[i][j] = fmaf(a[i], b[j], acc[i][j]);
        }
        __syncthreads();
    }

    float bsum[4];
    #pragma unroll
    for (int j = 0; j < 4; ++j)
        bsum[j] = bih[n0 + cc0 + j] + bhh[n0 + cc0 + j];

    #pragma unroll
    for (int i = 0; i < 4; ++i)
        #pragma unroll
        for (int j = 0; j < 4; ++j)
            g_xp[(size_t)(m0 + rr0 + i) * 2048 + (n0 + cc0 + j)] = acc[i][j] + bsum[j];
}

// ============================================================================
// barrier-counter reset (runs before the persistent kernel each launch so
// graph replays are deterministic)
// ============================================================================
__global__ void reset_kernel() { g_bar = 0u; }

// ============================================================================
// Kernel B: persistent recurrence. 128 CTAs (1/SM, co-resident), 256 threads.
//   CTA ct owns hidden slice jb..jb+8 (all 4 gates -> 32 W_hh rows, SMEM-resident)
//   and batch slice bb..bb+16. c-slice lives in SMEM for the whole kernel.
//   Per step: load h (L2, __ldcg) -> 8-way-K-split GEMM -> SMEM reduce ->
//   gates/elementwise -> write h to double buffer + outputs -> grid barrier.
// ============================================================================
__global__ __launch_bounds__(256) void lstm_rec_kernel(
    const float* __restrict__ h0,
    const float* __restrict__ c0,
    const float* __restrict__ Whh,
    float* __restrict__ out,
    long long out_size)
{
    extern __shared__ float sm[];
    float* Ws  = sm;                       // 32 * 513
    float* Hs  = Ws  + 32 * 513;           // 16 * 513
    float* Red = Hs  + 16 * 513;           // up to (7*32+31)*17+15 -> 4352
    float* Gs  = Red + 4352;               // 512 (gate partial sums: r*16+b)
    float* Cs  = Gs  + 512;                // 128 (c slice: b*8+j)

    const int tid = threadIdx.x;
    const int ct  = blockIdx.x;
    const int jb  = (ct >> 1) * 8;         // 64 hidden groups of 8
    const int bb  = (ct & 1) * 16;         // 2 batch groups of 16

    // ---- one-time: load this CTA's 32 W_hh rows into SMEM (row r = q*8+j) ----
    for (int idx = tid; idx < 32 * 512; idx += 256) {
        int r = idx >> 9, k = idx & 511;
        int q = r >> 3,  j = r & 7;
        Ws[r * 513 + k] = Whh[(size_t)(q * 512 + jb + j) * 512 + k];
    }
    // ---- one-time: load c slice ----
    const int jj  = tid & 7;
    const int bbt = tid >> 3;
    if (tid < 128)
        Cs[bbt * 8 + jj] = c0[(bb + bbt) * 512 + jb + jj];
    __syncthreads();

    const int gid  = tid >> 5;             // K-split group (8 groups of 64 k)
    const int lane = tid & 31;
    const int tm   = lane & 7;             // 4-row slice of the 32 rows
    const int tn   = lane >> 3;            // 4-batch slice of the 16 batches

    for (int t = 0; t < T_STEPS; ++t) {
        // prefetch this cell's x_proj gate values early (hidden behind GEMM)
        float xq0 = 0.f, xq1 = 0.f, xq2 = 0.f, xq3 = 0.f;
        if (tid < 128) {
            size_t base = ((size_t)t * 32 + bb + bbt) * 2048 + jb + jj;
            xq0 = __ldcs(&g_xp[base]);
            xq1 = __ldcs(&g_xp[base + 512]);
            xq2 = __ldcs(&g_xp[base + 1024]);
            xq3 = __ldcs(&g_xp[base + 1536]);
        }

        // load h slice (bypass L1: cross-step coherence via L2)
        const float* hsrc = (t == 0) ? h0 : g_h[t & 1];
        for (int i4 = tid; i4 < 16 * 128; i4 += 256) {
            int b  = i4 >> 7;
            int k4 = (i4 & 127) << 2;
            float4 v = __ldcg(reinterpret_cast<const float4*>(hsrc + (bb + b) * 512 + k4));
            float* d = &Hs[b * 513 + k4];
            d[0] = v.x; d[1] = v.y; d[2] = v.z; d[3] = v.w;
        }
        __syncthreads();

        // ---- GEMM partial: 4x4 per-thread tile over this group's 64-k chunk ----
        float acc[4][4];
        #pragma unroll
        for (int i = 0; i < 4; ++i)
            #pragma unroll
            for (int j = 0; j < 4; ++j) acc[i][j] = 0.f;

        const float* wp = &Ws[(tm * 4) * 513 + (gid << 6)];
        const float* hp = &Hs[(tn * 4) * 513 + (gid << 6)];
        #pragma unroll 4
        for (int k = 0; k < 64; ++k) {
            float a[4], b[4];
            #pragma unroll
            for (int i = 0; i < 4; ++i) a[i] = wp[i * 513 + k];
            #pragma unroll
            for (int j = 0; j < 4; ++j) b[j] = hp[j * 513 + k];
            #pragma unroll
            for (int i = 0; i < 4; ++i)
                #pragma unroll
                for (int j = 0; j < 4; ++j)
                    acc[i][j] = fmaf(a[i], b[j], acc[i][j]);
        }

        // store partials (padded stride 17 to soften STS bank conflicts)
        #pragma unroll
        for (int i = 0; i < 4; ++i)
            #pragma unroll
            for (int j = 0; j < 4; ++j)
                Red[(gid * 32 + tm * 4 + i) * 17 + (tn * 4 + j)] = acc[i][j];
        __syncthreads();

        // ---- reduce across 8 K-groups ----
        for (int o = tid; o < 512; o += 256) {
            int r = o >> 4, b = o & 15;
            float s = 0.f;
            #pragma unroll
            for (int g = 0; g < 8; ++g) s += Red[(g * 32 + r) * 17 + b];
            Gs[o] = s;   // Gs[r*16+b], r = q*8+j
        }
        __syncthreads();

        // ---- elementwise LSTM cell update (one thread per (j,b) cell) ----
        if (tid < 128) {
            const int j = jj, b = bbt;
            float zi = xq0 + Gs[(     j) * 16 + b];
            float zf = xq1 + Gs[( 8 + j) * 16 + b];
            float zg = xq2 + Gs[(16 + j) * 16 + b];
            float zo = xq3 + Gs[(24 + j) * 16 + b];
            float ig = 1.f / (1.f + __expf(-zi));
            float fg = 1.f / (1.f + __expf(-zf));
            float gg = tanhf(zg);
            float og = 1.f / (1.f + __expf(-zo));
            float cn = fg * Cs[b * 8 + j] + ig * gg;
            Cs[b * 8 + j] = cn;
            float hn = og * tanhf(cn);

            g_h[(t + 1) & 1][(bb + b) * 512 + jb + j] = hn;
            out[((size_t)t * 32 + bb + b) * 512 + jb + j] = hn;

            if (t == T_STEPS - 1) {
                long long need = (long long)T_STEPS * BATCH * HID + 2LL * BATCH * HID;
                if (out_size >= need) {
                    size_t ob = (size_t)T_STEPS * BATCH * HID;
                    out[ob + (bb + b) * 512 + jb + j]               = hn;  // h_f
                    out[ob + BATCH * HID + (bb + b) * 512 + jb + j] = cn;  // c_f
                }
            }
        }

        // ---- grid barrier (monotonic counter; skip after last step) ----
        if (t < T_STEPS - 1) {
            __threadfence();
            __syncthreads();
            if (tid == 0) {
                atomicAdd(&g_bar, 1u);
                unsigned target = (unsigned)(t + 1) * 128u;
                while (*((volatile unsigned*)&g_bar) < target) { }
            }
            __syncthreads();
        }
    }
}

// ============================================================================
extern "C" void kernel_launch(void* const* d_in, const int* in_sizes, int n_in,
                              void* d_out, int out_size)
{
    const float* seq = (const float*)d_in[0];
    const float* h0  = (const float*)d_in[1];
    const float* c0  = (const float*)d_in[2];
    const float* Wih = (const float*)d_in[3];
    const float* Whh = (const float*)d_in[4];
    const float* bih = (const float*)d_in[5];
    const float* bhh = (const float*)d_in[6];
    float* out = (float*)d_out;
    (void)in_sizes; (void)n_in;

    // Kernel A: x_proj for all timesteps
    dim3 gA(2048 / 64, (T_STEPS * BATCH) / 64);   // (32, 1024)
    xproj_kernel<<<gA, 256>>>(seq, Wih, bih, bhh);

    // reset grid-barrier counter (deterministic across graph replays)
    reset_kernel<<<1, 1>>>();

    // Kernel B: persistent recurrence
    size_t smem = (size_t)(32 * 513 + 16 * 513 + 4352 + 512 + 128) * sizeof(float);
    cudaFuncSetAttribute(lstm_rec_kernel,
                         cudaFuncAttributeMaxDynamicSharedMemorySize, (int)smem);
    lstm_rec_kernel<<<128, 256, smem>>>(h0, c0, Whh, out, (long long)out_size);
}

// round 2
// speedup vs baseline: 1.3703x; 1.3703x over previous
#include <cuda_runtime.h>
#include <cstdint>

#define T_STEPS 2048
#define BATCH   32
#define INDIM   512
#define HID     512
#define G4      2048   // 4*HID

typedef unsigned long long u64;

// packed f32x2 helpers (sm_103a packed fp32 pipe: 2x FFMA throughput)
__device__ __forceinline__ u64 pk2(float x) {
    u64 r; asm("mov.b64 %0, {%1, %1};" : "=l"(r) : "f"(x)); return r;
}
__device__ __forceinline__ void ffma2(u64& d, u64 a, u64 b, u64 c) {
    asm("fma.rn.f32x2 %0, %1, %2, %3;" : "=l"(d) : "l"(a), "l"(b), "l"(c));
}
__device__ __forceinline__ void fadd2(u64& d, u64 a, u64 b) {
    asm("add.rn.f32x2 %0, %1, %2;" : "=l"(d) : "l"(a), "l"(b));
}
__device__ __forceinline__ float2 up2(u64 v) {
    float2 f; asm("mov.b64 {%0, %1}, %2;" : "=f"(f.x), "=f"(f.y) : "l"(v)); return f;
}

// -------- persistent device scratch --------
__device__ float    g_xp[(size_t)T_STEPS * BATCH * G4];   // x_proj[t][b][g]
__device__ float    g_hT[2][HID * BATCH];                 // h transposed: [k][b], double buffered
__device__ unsigned g_bar;                                // grid barrier counter

// ============================================================================
// Kernel A: x_proj = seq @ W_ih^T + (b_ih + b_hh)
//   128M x 64N x 32K tiles, 256 threads, 8x4 per-thread tile, f32x2 math.
//   SMEM tiles stored K-major with XOR swizzle (conflict-free STS + LDS.128).
// ============================================================================
__global__ __launch_bounds__(256) void xproj_kernel(
    const float* __restrict__ seq,
    const float* __restrict__ Wih,
    const float* __restrict__ bih,
    const float* __restrict__ bhh)
{
    __shared__ float As[32 * 128];   // [k][m], word = k*128 + (m ^ (((k>>2)&7)<<2))
    __shared__ float Bs[32 * 64];    // [k][n], word = k*64  + (n ^ (((k>>2)&7)<<2))

    const int tid = threadIdx.x;
    const int m0g = blockIdx.y * 128;
    const int n0g = blockIdx.x * 64;
    const int tx  = tid & 15;        // n: tx*4
    const int ty  = tid >> 4;        // m: ty*8

    u64 acc[4][4];
    #pragma unroll
    for (int i = 0; i < 4; ++i)
        #pragma unroll
        for (int j = 0; j < 4; ++j) acc[i][j] = 0ull;

    for (int kb = 0; kb < 512; kb += 32) {
        // ---- A tile: 128m x 32k, transpose to K-major with swizzle ----
        #pragma unroll
        for (int i = 0; i < 4; ++i) {
            int flat = tid + i * 256;            // [0,1024)
            int kq = flat & 7;                   // k0 = kq*4
            int m  = flat >> 3;                  // [0,128)
            float4 v = *(const float4*)(seq + (size_t)(m0g + m) * 512 + kb + kq * 4);
            int base = (kq * 4) * 128 + (m ^ (kq << 2));
            As[base        ] = v.x;
            As[base + 128  ] = v.y;
            As[base + 256  ] = v.z;
            As[base + 384  ] = v.w;
        }
        // ---- B tile: 64n x 32k ----
        #pragma unroll
        for (int i = 0; i < 2; ++i) {
            int flat = tid + i * 256;            // [0,512)
            int kq = flat & 7;
            int n  = flat >> 3;                  // [0,64)
            float4 v = *(const float4*)(Wih + (size_t)(n0g + n) * 512 + kb + kq * 4);
            int base = (kq * 4) * 64 + (n ^ (kq << 2));
            Bs[base       ] = v.x;
            Bs[base + 64  ] = v.y;
            Bs[base + 128 ] = v.z;
            Bs[base + 192 ] = v.w;
        }
        __syncthreads();

        #pragma unroll
        for (int kk = 0; kk < 32; ++kk) {
            const int c = ((kk >> 2) & 7) << 2;
            ulonglong2 A0 = *(const ulonglong2*)(As + kk * 128 + ((ty * 8    ) ^ c));
            ulonglong2 A1 = *(const ulonglong2*)(As + kk * 128 + ((ty * 8 + 4) ^ c));
            float4 bv     = *(const float4*)    (Bs + kk * 64  + ((tx * 4    ) ^ c));
            u64 b0 = pk2(bv.x), b1 = pk2(bv.y), b2 = pk2(bv.z), b3 = pk2(bv.w);
            ffma2(acc[0][0], A0.x, b0, acc[0][0]);
            ffma2(acc[0][1], A0.x, b1, acc[0][1]);
            ffma2(acc[0][2], A0.x, b2, acc[0][2]);
            ffma2(acc[0][3], A0.x, b3, acc[0][3]);
            ffma2(acc[1][0], A0.y, b0, acc[1][0]);
            ffma2(acc[1][1], A0.y, b1, acc[1][1]);
            ffma2(acc[1][2], A0.y, b2, acc[1][2]);
            ffma2(acc[1][3], A0.y, b3, acc[1][3]);
            ffma2(acc[2][0], A1.x, b0, acc[2][0]);
            ffma2(acc[2][1], A1.x, b1, acc[2][1]);
            ffma2(acc[2][2], A1.x, b2, acc[2][2]);
            ffma2(acc[2][3], A1.x, b3, acc[2][3]);
            ffma2(acc[3][0], A1.y, b0, acc[3][0]);
            ffma2(acc[3][1], A1.y, b1, acc[3][1]);
            ffma2(acc[3][2], A1.y, b2, acc[3][2]);
            ffma2(acc[3][3], A1.y, b3, acc[3][3]);
        }
        __syncthreads();
    }

    float bs[4];
    #pragma unroll
    for (int j = 0; j < 4; ++j)
        bs[j] = bih[n0g + tx * 4 + j] + bhh[n0g + tx * 4 + j];

    #pragma unroll
    for (int mp = 0; mp < 4; ++mp) {
        float2 p0 = up2(acc[mp][0]);
        float2 p1 = up2(acc[mp][1]);
        float2 p2 = up2(acc[mp][2]);
        float2 p3 = up2(acc[mp][3]);
        float4 r0 = make_float4(p0.x + bs[0], p1.x + bs[1], p2.x + bs[2], p3.x + bs[3]);
        float4 r1 = make_float4(p0.y + bs[0], p1.y + bs[1], p2.y + bs[2], p3.y + bs[3]);
        size_t row0 = (size_t)(m0g + ty * 8 + 2 * mp) * 2048 + n0g + tx * 4;
        __stcs((float4*)(g_xp + row0), r0);
        __stcs((float4*)(g_xp + row0 + 2048), r1);
    }
}

// ============================================================================
__global__ void reset_kernel() { g_bar = 0u; }

// ============================================================================
// Kernel B: persistent recurrence. 128 CTAs x 256 threads, f32x2 math.
//   CTA: hidden slice jb..jb+8 (32 W_hh rows), batch slice bb..bb+16.
//   W_hh and h both K-major in SMEM, XOR-swizzled; h lives transposed [k][b]
//   in global (written by the cell threads each step), so the per-step fill
//   is coalesced float4 loads + STS.128.
//   16 K-split groups x 16 lanes; thread tile 8r x 4b.
// ============================================================================
__global__ __launch_bounds__(256) void lstm_rec_kernel(
    const float* __restrict__ h0,
    const float* __restrict__ c0,
    const float* __restrict__ Whh,
    float* __restrict__ out,
    long long out_size)
{
    extern __shared__ float sm[];
    float* Ws  = sm;                         // 512*32: [k][r], r^(((k>>5)&1)<<2)
    float* Hs  = Ws + 512 * 32;              // 512*32: [k][b(16)+pad], b^(((k>>5)&1)<<4)
    u64*   Red = (u64*)(Hs + 512 * 32);      // 16 groups * 16 r-pairs * 17 (b+pad)
    float* Gs  = (float*)(Red + 16 * 16 * 17); // 512: gates [r*16+b]
    float* Cs  = Gs + 512;                   // 128: c slice [b*8+j]

    const int tid = threadIdx.x;
    const int ct  = blockIdx.x;
    const int jb  = (ct >> 1) * 8;
    const int bb  = (ct & 1) * 16;

    // ---- one-time: W_hh rows -> K-major swizzled SMEM ----
    for (int idx = tid; idx < 32 * 512; idx += 256) {
        int r = idx & 31, k = idx >> 5;
        int q = r >> 3, j = r & 7;
        float w = Whh[(size_t)(q * 512 + jb + j) * 512 + k];
        Ws[k * 32 + (r ^ (((k >> 5) & 1) << 2))] = w;
    }
    // ---- one-time: c slice ----
    const int jj  = tid & 7;
    const int bbt = tid >> 3;
    if (tid < 128) Cs[bbt * 8 + jj] = c0[(bb + bbt) * 512 + jb + jj];
    // ---- one-time: Hs from h0 (transpose; slow scalar path, once) ----
    for (int idx = tid; idx < 512 * 16; idx += 256) {
        int b = idx & 15, k = idx >> 4;
        Hs[k * 32 + (b ^ (((k >> 5) & 1) << 4))] = h0[(bb + b) * 512 + k];
    }
    __syncthreads();

    const int gid = tid >> 4;          // K-group: k in [gid*32, gid*32+32)
    const int l16 = tid & 15;
    const int tm  = l16 & 3;           // r0 = tm*8
    const int tn  = l16 >> 2;          // b0 = tn*4
    const int cA  = (gid & 1) << 2;    // ((k>>5)&1)<<2 is constant per group
    const int cH  = (gid & 1) << 4;
    const float* wsp = Ws + (size_t)gid * 32 * 32;
    const float* hsp = Hs + (size_t)gid * 32 * 32;
    const int aw0 = (tm * 8    ) ^ cA;
    const int aw1 = (tm * 8 + 4) ^ cA;
    const int hw  = (tn * 4    ) ^ cH;

    for (int t = 0; t < T_STEPS; ++t) {
        // prefetch x_proj gate values for this cell (hidden behind GEMM)
        float xq0 = 0.f, xq1 = 0.f, xq2 = 0.f, xq3 = 0.f;
        if (tid < 128) {
            size_t base = ((size_t)t * 32 + bb + bbt) * 2048 + jb + jj;
            xq0 = __ldcs(&g_xp[base]);
            xq1 = __ldcs(&g_xp[base + 512]);
            xq2 = __ldcs(&g_xp[base + 1024]);
            xq3 = __ldcs(&g_xp[base + 1536]);
        }

        if (t > 0) {
            // fill Hs from transposed global h buffer (coalesced, STS.128)
            const float* hsrc = g_hT[t & 1];
            #pragma unroll
            for (int i = 0; i < 8; ++i) {
                int flat = tid + i * 256;      // [0,2048)
                int q  = flat & 3;             // 4-float chunk within 16 b
                int kr = flat >> 2;            // [0,512)
                float4 v = __ldcg((const float4*)(hsrc + kr * 32 + bb + q * 4));
                *(float4*)(Hs + kr * 32 + ((q * 4) ^ (((kr >> 5) & 1) << 4))) = v;
            }
            __syncthreads();
        }

        // ---- per-group GEMM: 8r x 4b tile over 32 k, f32x2 packed along r ----
        u64 acc[4][4];
        #pragma unroll
        for (int i = 0; i < 4; ++i)
            #pragma unroll
            for (int j = 0; j < 4; ++j) acc[i][j] = 0ull;

        #pragma unroll 8
        for (int k = 0; k < 32; ++k) {
            ulonglong2 A0 = *(const ulonglong2*)(wsp + k * 32 + aw0);
            ulonglong2 A1 = *(const ulonglong2*)(wsp + k * 32 + aw1);
            float4 bv     = *(const float4*)    (hsp + k * 32 + hw);
            u64 b0 = pk2(bv.x), b1 = pk2(bv.y), b2 = pk2(bv.z), b3 = pk2(bv.w);
            ffma2(acc[0][0], A0.x, b0, acc[0][0]);
            ffma2(acc[0][1], A0.x, b1, acc[0][1]);
            ffma2(acc[0][2], A0.x, b2, acc[0][2]);
            ffma2(acc[0][3], A0.x, b3, acc[0][3]);
            ffma2(acc[1][0], A0.y, b0, acc[1][0]);
            ffma2(acc[1][1], A0.y, b1, acc[1][1]);
            ffma2(acc[1][2], A0.y, b2, acc[1][2]);
            ffma2(acc[1][3], A0.y, b3, acc[1][3]);
            ffma2(acc[2][0], A1.x, b0, acc[2][0]);
            ffma2(acc[2][1], A1.x, b1, acc[2][1]);
            ffma2(acc[2][2], A1.x, b2, acc[2][2]);
            ffma2(acc[2][3], A1.x, b3, acc[2][3]);
            ffma2(acc[3][0], A1.y, b0, acc[3][0]);
            ffma2(acc[3][1], A1.y, b1, acc[3][1]);
            ffma2(acc[3][2], A1.y, b2, acc[3][2]);
            ffma2(acc[3][3], A1.y, b3, acc[3][3]);
        }

        // ---- store packed partials ----
        #pragma unroll
        for (int mp = 0; mp < 4; ++mp)
            #pragma unroll
            for (int n = 0; n < 4; ++n)
                Red[(gid * 16 + tm * 4 + mp) * 17 + (tn * 4 + n)] = acc[mp][n];
        __syncthreads();

        // ---- reduce 16 groups (f32x2 adds), one output pair per thread ----
        {
            int rp = tid >> 4, b = tid & 15;
            u64 s = Red[rp * 17 + b];
            #pragma unroll
            for (int g = 1; g < 16; ++g)
                fadd2(s, s, Red[(g * 16 + rp) * 17 + b]);
            float2 f = up2(s);
            Gs[(rp * 2    ) * 16 + b] = f.x;
            Gs[(rp * 2 + 1) * 16 + b] = f.y;
        }
        __syncthreads();

        // ---- LSTM cell update (one thread per (j,b) cell) ----
        if (tid < 128) {
            const int j = jj, b = bbt;
            float zi = xq0 + Gs[(     j) * 16 + b];
            float zf = xq1 + Gs[( 8 + j) * 16 + b];
            float zg = xq2 + Gs[(16 + j) * 16 + b];
            float zo = xq3 + Gs[(24 + j) * 16 + b];
            float ig = 1.f / (1.f + __expf(-zi));
            float fg = 1.f / (1.f + __expf(-zf));
            float gg = tanhf(zg);
            float og = 1.f / (1.f + __expf(-zo));
            float cn = fg * Cs[b * 8 + j] + ig * gg;
            Cs[b * 8 + j] = cn;
            float hn = og * tanhf(cn);

            g_hT[(t + 1) & 1][(jb + j) * 32 + bb + b] = hn;
            out[((size_t)t * 32 + bb + b) * 512 + jb + j] = hn;

            if (t == T_STEPS - 1) {
                long long need = (long long)T_STEPS * BATCH * HID + 2LL * BATCH * HID;
                if (out_size >= need) {
                    size_t ob = (size_t)T_STEPS * BATCH * HID;
                    out[ob + (bb + b) * 512 + jb + j]               = hn;  // h_f
                    out[ob + BATCH * HID + (bb + b) * 512 + jb + j] = cn;  // c_f
                }
            }
        }

        // ---- grid barrier ----
        if (t < T_STEPS - 1) {
            __threadfence();
            __syncthreads();
            if (tid == 0) {
                atomicAdd(&g_bar, 1u);
                unsigned target = (unsigned)(t + 1) * 128u;
                while (*((volatile unsigned*)&g_bar) < target) { }
            }
            __syncthreads();
        }
    }
}

// ============================================================================
extern "C" void kernel_launch(void* const* d_in, const int* in_sizes, int n_in,
                              void* d_out, int out_size)
{
    const float* seq = (const float*)d_in[0];
    const float* h0  = (const float*)d_in[1];
    const float* c0  = (const float*)d_in[2];
    const float* Wih = (const float*)d_in[3];
    const float* Whh = (const float*)d_in[4];
    const float* bih = (const float*)d_in[5];
    const float* bhh = (const float*)d_in[6];
    float* out = (float*)d_out;
    (void)in_sizes; (void)n_in;

    dim3 gA(2048 / 64, (T_STEPS * BATCH) / 128);   // (32, 512)
    xproj_kernel<<<gA, 256>>>(seq, Wih, bih, bhh);

    reset_kernel<<<1, 1>>>();

    size_t smem = (size_t)(512 * 32 + 512 * 32 + 512) * sizeof(float)
                + (size_t)(16 * 16 * 17) * sizeof(u64)
                + (size_t)128 * sizeof(float);
    cudaFuncSetAttribute(lstm_rec_kernel,
                         cudaFuncAttributeMaxDynamicSharedMemorySize, (int)smem);
    lstm_rec_kernel<<<128, 256, smem>>>(h0, c0, Whh, out, (long long)out_size);
}